// round 16
// baseline (speedup 1.0000x reference)
#include <cuda_runtime.h>

#define Bn 4
#define Cn 16
#define Kn 100
#define Pn 76800
#define ITERS 10
#define BW2F ((float)(0.16*0.16))

#define TPB 128
#define IPT 4                      // 4 points/thread
#define XB  (Pn/(TPB*IPT))         // 150 blocks per batch
#define MSTR 20                    // floats per k: {-2m x16, mn2, 0, pad2}

typedef unsigned long long u64;

// ---- device scratch (zero-initialized at load; every launch restores the
//      zeros it consumed -> replay-safe with NO init kernel) ----
__device__ float g_num[ITERS][Bn*Kn*Cn];
__device__ float g_den[ITERS][Bn*Kn];
__device__ unsigned g_barcnt[Bn * 32];     // monotonic ticket counters

// ---- packed f32x2 helpers ----
__device__ __forceinline__ u64 pk2(float lo, float hi) {
    u64 r; asm("mov.b64 %0,{%1,%2};" : "=l"(r) : "f"(lo), "f"(hi)); return r;
}
__device__ __forceinline__ void up2(u64 v, float& lo, float& hi) {
    asm("mov.b64 {%0,%1},%2;" : "=f"(lo), "=f"(hi) : "l"(v));
}
__device__ __forceinline__ u64 f2fma(u64 a, u64 b, u64 c) {
    u64 d; asm("fma.rn.f32x2 %0,%1,%2,%3;" : "=l"(d) : "l"(a), "l"(b), "l"(c)); return d;
}
__device__ __forceinline__ u64 f2mul(u64 a, u64 b) {
    u64 d; asm("mul.rn.f32x2 %0,%1,%2;" : "=l"(d) : "l"(a), "l"(b)); return d;
}

// ticket-based per-batch barrier: counter only grows -> no reset needed,
// replay-safe. Round r's XB arrivals get tickets in [r*XB,(r+1)*XB).
__device__ __forceinline__ void batchbar(int b) {
    __syncthreads();
    if (threadIdx.x == 0) {
        __threadfence();
        unsigned t = atomicAdd(&g_barcnt[b * 32], 1u);
        unsigned target = (t / XB + 1u) * XB;
        volatile unsigned* p = &g_barcnt[b * 32];
        while (*p < target) __nanosleep(16);
        __threadfence();
    }
    __syncthreads();
}

// single-chain shifted distance: s = mn2 + sum_c f_c * (-2 m_c)
__device__ __forceinline__ float dchain1(const u64 (&f)[8],
                                         ulonglong2 mA, ulonglong2 mB,
                                         ulonglong2 mC, ulonglong2 mD,
                                         u64 mnz) {
    u64 v = f2fma(f[0], mA.x, mnz);
    v = f2fma(f[1], mA.y, v);
    v = f2fma(f[2], mB.x, v);
    v = f2fma(f[3], mB.y, v);
    v = f2fma(f[4], mC.x, v);
    v = f2fma(f[5], mC.y, v);
    v = f2fma(f[6], mD.x, v);
    v = f2fma(f[7], mD.y, v);
    float lo, hi; up2(v, lo, hi);
    return lo + hi;
}

// rare slow path: rescan all Kn means for one point, exact hit atomics
__device__ __noinline__ void rescan(const u64 (&f)[8], float thr,
                                    const float* s_m, int b, int it) {
    for (int kl = 0; kl < Kn; kl++) {
        const ulonglong2* mp = (const ulonglong2*)&s_m[kl * MSTR];
        u64 mnz = *(const u64*)&s_m[kl * MSTR + 16];
        float s = dchain1(f, mp[0], mp[1], mp[2], mp[3], mnz);
        if (s < thr) {
            int kg = b * Kn + kl;
            atomicAdd(&g_den[it][kg], 1.0f);
#pragma unroll
            for (int j = 0; j < 8; j++) {
                float v0, v1; up2(f[j], v0, v1);
                atomicAdd(&g_num[it][kg * Cn + 2 * j],     v0);
                atomicAdd(&g_num[it][kg * Cn + 2 * j + 1], v1);
            }
        }
    }
}

// ---------------------------------------------------------------------------
// Single-launch persistent kernel. Point LDGs issued FIRST (latency hidden
// under idx-detect + seed-gather). Scans track (min via FMNMX chain, argmin
// via off-chain select); bitwise fixed point => last scan's results ARE the
// label results. Fallback label scan only without convergence.
// ---------------------------------------------------------------------------
__global__ void __launch_bounds__(TPB, 5)
fused_kernel(const float* __restrict__ feat, const void* __restrict__ idxraw,
             float* __restrict__ out, int out_size) {
    const int b = blockIdx.y;
    __shared__ __align__(16) float s_m[Kn * MSTR];
    __shared__ int s_cnt;
    __shared__ int s_is64;

    // ---- issue point loads FIRST (independent of smem/barriers) ----
    const int pbase = blockIdx.x * (TPB * IPT) + 4 * threadIdx.x;
    const float4* fb4 = (const float4*)(feat + (size_t)b * Cn * Pn + pbase);
    float4 va0 = fb4[0],              vb0 = fb4[(size_t)1 * (Pn / 4)];
    float4 va1 = fb4[(size_t)2  * (Pn / 4)], vb1 = fb4[(size_t)3  * (Pn / 4)];
    float4 va2 = fb4[(size_t)4  * (Pn / 4)], vb2 = fb4[(size_t)5  * (Pn / 4)];
    float4 va3 = fb4[(size_t)6  * (Pn / 4)], vb3 = fb4[(size_t)7  * (Pn / 4)];
    float4 va4 = fb4[(size_t)8  * (Pn / 4)], vb4 = fb4[(size_t)9  * (Pn / 4)];
    float4 va5 = fb4[(size_t)10 * (Pn / 4)], vb5 = fb4[(size_t)11 * (Pn / 4)];
    float4 va6 = fb4[(size_t)12 * (Pn / 4)], vb6 = fb4[(size_t)13 * (Pn / 4)];
    float4 va7 = fb4[(size_t)14 * (Pn / 4)], vb7 = fb4[(size_t)15 * (Pn / 4)];

    // ---- idx width detection (per block; 1600 B, L2-hot) ----
    if (threadIdx.x == 0) s_is64 = 1;
    __syncthreads();
    {
        const long long* ip = (const long long*)idxraw;
        for (int i = threadIdx.x; i < 200; i += TPB) {
            long long v = ip[i];
            if (v < 0 || v >= (long long)Pn) s_is64 = 0;
        }
    }
    __syncthreads();

    // ---- it=0 prologue: gather seeds from feat -> {-2m, mn2} table ----
    for (int kl = threadIdx.x; kl < Kn; kl += TPB) {
        int t = b * Kn + kl;
        long long idx = s_is64 ? ((const long long*)idxraw)[t]
                               : (long long)((const int*)idxraw)[t];
        const float* fb = feat + (size_t)b * Cn * Pn + (size_t)idx;
        float mn2 = 0.0f;
#pragma unroll
        for (int c = 0; c < Cn; c++) {
            float m = fb[(size_t)c * Pn];
            s_m[kl * MSTR + c] = -2.0f * m;
            mn2 += m * m;
        }
        s_m[kl * MSTR + 16] = mn2;
        s_m[kl * MSTR + 17] = 0.0f;
    }

    // ---- pack the preloaded points into channel pairs ----
    u64 f0[8], f1[8], f2[8], f3[8];
    {
        float4 va[8] = {va0, va1, va2, va3, va4, va5, va6, va7};
        float4 vb[8] = {vb0, vb1, vb2, vb3, vb4, vb5, vb6, vb7};
#pragma unroll
        for (int j = 0; j < 8; j++) {
            f0[j] = pk2(va[j].x, vb[j].x);
            f1[j] = pk2(va[j].y, vb[j].y);
            f2[j] = pk2(va[j].z, vb[j].z);
            f3[j] = pk2(va[j].w, vb[j].w);
        }
    }
    float fn2_0, fn2_1, fn2_2, fn2_3;
    {
        u64 q0 = f2mul(f0[0], f0[0]), q1 = f2mul(f1[0], f1[0]);
        u64 q2 = f2mul(f2[0], f2[0]), q3 = f2mul(f3[0], f3[0]);
#pragma unroll
        for (int j = 1; j < 8; j++) {
            q0 = f2fma(f0[j], f0[j], q0);
            q1 = f2fma(f1[j], f1[j], q1);
            q2 = f2fma(f2[j], f2[j], q2);
            q3 = f2fma(f3[j], f3[j], q3);
        }
        float lo, hi;
        up2(q0, lo, hi); fn2_0 = lo + hi;
        up2(q1, lo, hi); fn2_1 = lo + hi;
        up2(q2, lo, hi); fn2_2 = lo + hi;
        up2(q3, lo, hi); fn2_3 = lo + hi;
    }
    const float t0 = BW2F - fn2_0, t1 = BW2F - fn2_1;
    const float t2 = BW2F - fn2_2, t3 = BW2F - fn2_3;
    __syncthreads();

    float s0m, s1m, s2m, s3m;
    int i0, i1, i2, i3;
    bool done = false;

    for (int it = 0; it < ITERS; it++) {
        // scan: FMNMX min chain + off-chain index select
        s0m = 3.4e38f; s1m = 3.4e38f; s2m = 3.4e38f; s3m = 3.4e38f;
        i0 = 0; i1 = 0; i2 = 0; i3 = 0;
#pragma unroll 4
        for (int kl = 0; kl < Kn; kl++) {
            const ulonglong2* mp = (const ulonglong2*)&s_m[kl * MSTR];
            ulonglong2 mA = mp[0], mB = mp[1], mC = mp[2], mD = mp[3];
            u64 mnz = *(const u64*)&s_m[kl * MSTR + 16];
            float s0 = dchain1(f0, mA, mB, mC, mD, mnz);
            float s1 = dchain1(f1, mA, mB, mC, mD, mnz);
            float s2 = dchain1(f2, mA, mB, mC, mD, mnz);
            float s3 = dchain1(f3, mA, mB, mC, mD, mnz);
            bool c0 = s0 < s0m, c1 = s1 < s1m, c2 = s2 < s2m, c3 = s3 < s3m;
            s0m = fminf(s0m, s0);  i0 = c0 ? kl : i0;
            s1m = fminf(s1m, s1);  i1 = c1 ? kl : i1;
            s2m = fminf(s2m, s2);  i2 = c2 ? kl : i2;
            s3m = fminf(s3m, s3);  i3 = c3 ? kl : i3;
        }
        if (s0m < t0) rescan(f0, t0, s_m, b, it);
        if (s1m < t1) rescan(f1, t1, s_m, b, it);
        if (s2m < t2) rescan(f2, t2, s_m, b, it);
        if (s3m < t3) rescan(f3, t3, s_m, b, it);

        // zero this batch's num/den[it+1] slice BEFORE arriving
        if (it + 1 < ITERS) {
            int base = b * Kn * Cn;
            for (int i = blockIdx.x * TPB + threadIdx.x; i < Kn * Cn; i += XB * TPB)
                g_num[it + 1][base + i] = 0.0f;
            for (int i = blockIdx.x * TPB + threadIdx.x; i < Kn; i += XB * TPB)
                g_den[it + 1][b * Kn + i] = 0.0f;
        }

        batchbar(b);          // scan[it] complete for this batch

        // prologue: means[it+1] from num/den[it]; old recovered from s_m
        if (threadIdx.x == 0) s_cnt = 0;
        __syncthreads();
        for (int kl = threadIdx.x; kl < Kn; kl += TPB) {
            int t = b * Kn + kl;
            float den = g_den[it][t];
            float dm = fmaxf(den, 1.0f);
            bool pos = den > 0.0f;
            bool same = true;
            float mn2 = 0.0f;
#pragma unroll
            for (int c = 0; c < Cn; c++) {
                float oldp = s_m[kl * MSTR + c];                // -2*old (exact)
                float nm = pos ? (g_num[it][t * Cn + c] / dm) : (-0.5f * oldp);
                float np = -2.0f * nm;
                s_m[kl * MSTR + c] = np;
                mn2 += nm * nm;
                same = same && (__float_as_uint(np) == __float_as_uint(oldp));
            }
            s_m[kl * MSTR + 16] = mn2;
            if (same) atomicAdd(&s_cnt, 1);
        }
        __syncthreads();
        if (s_cnt == Kn) { done = true; break; }  // final means == means[it]
    }

    // ---- fallback label scan (only if not converged in 10 iters) ----
    if (!done) {
        s0m = 3.4e38f; s1m = 3.4e38f; s2m = 3.4e38f; s3m = 3.4e38f;
        i0 = 0; i1 = 0; i2 = 0; i3 = 0;
#pragma unroll 4
        for (int kl = 0; kl < Kn; kl++) {
            const ulonglong2* mp = (const ulonglong2*)&s_m[kl * MSTR];
            ulonglong2 mA = mp[0], mB = mp[1], mC = mp[2], mD = mp[3];
            u64 mnz = *(const u64*)&s_m[kl * MSTR + 16];
            float s0 = dchain1(f0, mA, mB, mC, mD, mnz);
            float s1 = dchain1(f1, mA, mB, mC, mD, mnz);
            float s2 = dchain1(f2, mA, mB, mC, mD, mnz);
            float s3 = dchain1(f3, mA, mB, mC, mD, mnz);
            bool c0 = s0 < s0m, c1 = s1 < s1m, c2 = s2 < s2m, c3 = s3 < s3m;
            s0m = fminf(s0m, s0);  i0 = c0 ? kl : i0;
            s1m = fminf(s1m, s1);  i1 = c1 ? kl : i1;
            s2m = fminf(s2m, s2);  i2 = c2 ? kl : i2;
            s3m = fminf(s3m, s3);  i3 = c3 ? kl : i3;
        }
    }

    // ---- emit labels + means tail ----
    float* ob = out + (size_t)b * Pn + pbase;
    ob[0] = (s0m < t0) ? (float)(i0 + 1) : 0.0f;
    ob[1] = (s1m < t1) ? (float)(i1 + 1) : 0.0f;
    ob[2] = (s2m < t2) ? (float)(i2 + 1) : 0.0f;
    ob[3] = (s3m < t3) ? (float)(i3 + 1) : 0.0f;
    if (blockIdx.x == 0) {
        for (int i = threadIdx.x; i < Kn * Cn; i += TPB) {
            int o = Bn * Pn + b * Kn * Cn + i;
            if (o < out_size)
                out[o] = -0.5f * s_m[(i / Cn) * MSTR + (i % Cn)];
        }
    }

    // ---- epilogue: restore num/den[0] zeros for the next graph replay ----
    batchbar(b);
    {
        int base = b * Kn * Cn;
        for (int i = blockIdx.x * TPB + threadIdx.x; i < Kn * Cn; i += XB * TPB)
            g_num[0][base + i] = 0.0f;
        for (int i = blockIdx.x * TPB + threadIdx.x; i < Kn; i += XB * TPB)
            g_den[0][b * Kn + i] = 0.0f;
    }
}

extern "C" void kernel_launch(void* const* d_in, const int* in_sizes, int n_in,
                              void* d_out, int out_size) {
    const float* feat = (const float*)d_in[0];
    const void*  sidx = d_in[1];
    float* out = (float*)d_out;

    dim3 grid(XB, Bn);
    fused_kernel<<<grid, TPB>>>(feat, sidx, out, out_size);
}

// round 17
// speedup vs baseline: 1.0386x; 1.0386x over previous
#include <cuda_runtime.h>

#define Bn 4
#define Cn 16
#define Kn 100
#define Pn 76800
#define ITERS 10
#define BW2F ((float)(0.16*0.16))

#define TPB 128
#define IPT 4                      // 4 points/thread
#define XB  (Pn/(TPB*IPT))         // 150 blocks per batch
#define MSTR 20                    // floats per k: {-2m x16, mn2, 0, pad2}

typedef unsigned long long u64;

// ---- device scratch (zero-initialized at load; every launch restores the
//      zeros it consumed -> replay-safe, no init kernel) ----
__device__ float g_num[ITERS][Bn*Kn*Cn];
__device__ float g_den[ITERS][Bn*Kn];
__device__ unsigned g_barcnt[Bn * 32];     // monotonic ticket counters

// ---- packed f32x2 helpers ----
__device__ __forceinline__ u64 pk2(float lo, float hi) {
    u64 r; asm("mov.b64 %0,{%1,%2};" : "=l"(r) : "f"(lo), "f"(hi)); return r;
}
__device__ __forceinline__ void up2(u64 v, float& lo, float& hi) {
    asm("mov.b64 {%0,%1},%2;" : "=f"(lo), "=f"(hi) : "l"(v));
}
__device__ __forceinline__ u64 f2fma(u64 a, u64 b, u64 c) {
    u64 d; asm("fma.rn.f32x2 %0,%1,%2,%3;" : "=l"(d) : "l"(a), "l"(b), "l"(c)); return d;
}
__device__ __forceinline__ u64 f2mul(u64 a, u64 b) {
    u64 d; asm("mul.rn.f32x2 %0,%1,%2;" : "=l"(d) : "l"(a), "l"(b)); return d;
}

// ticket-based per-batch barrier: counter only grows -> no reset, replay-safe
__device__ __forceinline__ void batchbar(int b) {
    __syncthreads();
    if (threadIdx.x == 0) {
        __threadfence();
        unsigned t = atomicAdd(&g_barcnt[b * 32], 1u);
        unsigned target = (t / XB + 1u) * XB;
        volatile unsigned* p = &g_barcnt[b * 32];
        while (*p < target) __nanosleep(16);
        __threadfence();
    }
    __syncthreads();
}

// single-chain shifted distance: s = mn2 + sum_c f_c * (-2 m_c)
// Entirely inline asm -> ptxas cannot reassociate: bitwise reproducible.
__device__ __forceinline__ float dchain1(const u64 (&f)[8],
                                         ulonglong2 mA, ulonglong2 mB,
                                         ulonglong2 mC, ulonglong2 mD,
                                         u64 mnz) {
    u64 v = f2fma(f[0], mA.x, mnz);
    v = f2fma(f[1], mA.y, v);
    v = f2fma(f[2], mB.x, v);
    v = f2fma(f[3], mB.y, v);
    v = f2fma(f[4], mC.x, v);
    v = f2fma(f[5], mC.y, v);
    v = f2fma(f[6], mD.x, v);
    v = f2fma(f[7], mD.y, v);
    float lo, hi; up2(v, lo, hi);
    return lo + hi;
}

__device__ __forceinline__ float dchain_row(const u64 (&f)[8], const float* mk) {
    const ulonglong2* mp = (const ulonglong2*)mk;
    return dchain1(f, mp[0], mp[1], mp[2], mp[3], *(const u64*)(mk + 16));
}

// rare: rescan all Kn means for one point, exact hit atomics
__device__ __noinline__ void rescan(const u64 (&f)[8], float thr,
                                    const float* s_m, int b, int it) {
    for (int kl = 0; kl < Kn; kl++) {
        float s = dchain_row(f, &s_m[kl * MSTR]);
        if (s < thr) {
            int kg = b * Kn + kl;
            atomicAdd(&g_den[it][kg], 1.0f);
#pragma unroll
            for (int j = 0; j < 8; j++) {
                float v0, v1; up2(f[j], v0, v1);
                atomicAdd(&g_num[it][kg * Cn + 2 * j],     v0);
                atomicAdd(&g_num[it][kg * Cn + 2 * j + 1], v1);
            }
        }
    }
}

// rare: recover first-argmin by bitwise-identical recomputation.
// First k whose s compares numerically equal to the tracked min IS the
// first argmin (jnp.argmin semantics).
__device__ __noinline__ int find_argmin(const u64 (&f)[8], float smin,
                                        const float* s_m) {
    for (int kl = 0; kl < Kn; kl++)
        if (dchain_row(f, &s_m[kl * MSTR]) == smin) return kl;
    return 0;
}

// ---------------------------------------------------------------------------
// Single-launch persistent kernel. Hot k-loop: depth-1 prefetch of (mnz,mA),
// min tracked via FMNMX only; argmin/hits recovered post-loop (rare).
// Bitwise fixed point => last scan's mins ARE the label mins.
// ---------------------------------------------------------------------------
__global__ void __launch_bounds__(TPB, 5)
fused_kernel(const float* __restrict__ feat, const void* __restrict__ idxraw,
             float* __restrict__ out, int out_size) {
    const int b = blockIdx.y;
    __shared__ __align__(16) float s_m[(Kn + 1) * MSTR];   // +1 pad row
    __shared__ int s_cnt;
    __shared__ int s_is64;

    // ---- idx width detection (per block; 1600 B, L2-hot) ----
    if (threadIdx.x == 0) s_is64 = 1;
    __syncthreads();
    {
        const long long* ip = (const long long*)idxraw;
        for (int i = threadIdx.x; i < 200; i += TPB) {
            long long v = ip[i];
            if (v < 0 || v >= (long long)Pn) s_is64 = 0;
        }
    }
    __syncthreads();

    // ---- it=0 prologue: gather seeds -> {-2m, mn2}; zero pad row ----
    for (int kl = threadIdx.x; kl < Kn; kl += TPB) {
        int t = b * Kn + kl;
        long long idx = s_is64 ? ((const long long*)idxraw)[t]
                               : (long long)((const int*)idxraw)[t];
        const float* fb = feat + (size_t)b * Cn * Pn + (size_t)idx;
        float mn2 = 0.0f;
#pragma unroll
        for (int c = 0; c < Cn; c++) {
            float m = fb[(size_t)c * Pn];
            s_m[kl * MSTR + c] = -2.0f * m;
            mn2 += m * m;
        }
        s_m[kl * MSTR + 16] = mn2;
        s_m[kl * MSTR + 17] = 0.0f;
    }
    for (int i = threadIdx.x; i < MSTR; i += TPB)
        s_m[Kn * MSTR + i] = 0.0f;                        // pad row (prefetch target)

    // ---- load 4 consecutive points; channel-packed pairs ----
    const int pbase = blockIdx.x * (TPB * IPT) + 4 * threadIdx.x;
    const float4* fb4 = (const float4*)(feat + (size_t)b * Cn * Pn + pbase);
    u64 f0[8], f1[8], f2[8], f3[8];
#pragma unroll
    for (int c = 0; c < Cn; c += 2) {
        float4 va = fb4[(size_t)c * (Pn / 4)];
        float4 vb = fb4[(size_t)(c + 1) * (Pn / 4)];
        f0[c / 2] = pk2(va.x, vb.x);
        f1[c / 2] = pk2(va.y, vb.y);
        f2[c / 2] = pk2(va.z, vb.z);
        f3[c / 2] = pk2(va.w, vb.w);
    }
    float fn2_0, fn2_1, fn2_2, fn2_3;
    {
        u64 q0 = f2mul(f0[0], f0[0]), q1 = f2mul(f1[0], f1[0]);
        u64 q2 = f2mul(f2[0], f2[0]), q3 = f2mul(f3[0], f3[0]);
#pragma unroll
        for (int j = 1; j < 8; j++) {
            q0 = f2fma(f0[j], f0[j], q0);
            q1 = f2fma(f1[j], f1[j], q1);
            q2 = f2fma(f2[j], f2[j], q2);
            q3 = f2fma(f3[j], f3[j], q3);
        }
        float lo, hi;
        up2(q0, lo, hi); fn2_0 = lo + hi;
        up2(q1, lo, hi); fn2_1 = lo + hi;
        up2(q2, lo, hi); fn2_2 = lo + hi;
        up2(q3, lo, hi); fn2_3 = lo + hi;
    }
    const float t0 = BW2F - fn2_0, t1 = BW2F - fn2_1;
    const float t2 = BW2F - fn2_2, t3 = BW2F - fn2_3;
    __syncthreads();

    float s0m, s1m, s2m, s3m;
    bool done = false;

    for (int it = 0; it < ITERS; it++) {
        // ---- hot scan: min only, depth-1 prefetch of (mnz, mA) ----
        s0m = 3.4e38f; s1m = 3.4e38f; s2m = 3.4e38f; s3m = 3.4e38f;
        u64 p_mnz = *(const u64*)&s_m[16];
        ulonglong2 p_mA = *(const ulonglong2*)&s_m[0];
#pragma unroll 2
        for (int kl = 0; kl < Kn; kl++) {
            u64 mnz = p_mnz;
            ulonglong2 mA = p_mA;
            const float* nk = &s_m[(kl + 1) * MSTR];       // row Kn = pad
            p_mnz = *(const u64*)(nk + 16);
            p_mA = *(const ulonglong2*)nk;
            const ulonglong2* mp = (const ulonglong2*)&s_m[kl * MSTR];
            ulonglong2 mB = mp[1], mC = mp[2], mD = mp[3];
            float s0 = dchain1(f0, mA, mB, mC, mD, mnz);
            float s1 = dchain1(f1, mA, mB, mC, mD, mnz);
            float s2 = dchain1(f2, mA, mB, mC, mD, mnz);
            float s3 = dchain1(f3, mA, mB, mC, mD, mnz);
            s0m = fminf(s0m, s0);
            s1m = fminf(s1m, s1);
            s2m = fminf(s2m, s2);
            s3m = fminf(s3m, s3);
        }
        if (s0m < t0) rescan(f0, t0, s_m, b, it);
        if (s1m < t1) rescan(f1, t1, s_m, b, it);
        if (s2m < t2) rescan(f2, t2, s_m, b, it);
        if (s3m < t3) rescan(f3, t3, s_m, b, it);

        // zero this batch's num/den[it+1] slice BEFORE arriving
        if (it + 1 < ITERS) {
            int base = b * Kn * Cn;
            for (int i = blockIdx.x * TPB + threadIdx.x; i < Kn * Cn; i += XB * TPB)
                g_num[it + 1][base + i] = 0.0f;
            for (int i = blockIdx.x * TPB + threadIdx.x; i < Kn; i += XB * TPB)
                g_den[it + 1][b * Kn + i] = 0.0f;
        }

        batchbar(b);          // scan[it] complete for this batch

        // prologue: means[it+1] from num/den[it]; old recovered from s_m
        if (threadIdx.x == 0) s_cnt = 0;
        __syncthreads();
        for (int kl = threadIdx.x; kl < Kn; kl += TPB) {
            int t = b * Kn + kl;
            float den = g_den[it][t];
            float dm = fmaxf(den, 1.0f);
            bool pos = den > 0.0f;
            bool same = true;
            float mn2 = 0.0f;
#pragma unroll
            for (int c = 0; c < Cn; c++) {
                float oldp = s_m[kl * MSTR + c];            // -2*old (exact)
                float nm = pos ? (g_num[it][t * Cn + c] / dm) : (-0.5f * oldp);
                float np = -2.0f * nm;
                s_m[kl * MSTR + c] = np;
                mn2 += nm * nm;
                same = same && (__float_as_uint(np) == __float_as_uint(oldp));
            }
            s_m[kl * MSTR + 16] = mn2;
            if (same) atomicAdd(&s_cnt, 1);
        }
        __syncthreads();
        if (s_cnt == Kn) { done = true; break; }  // final means == means[it]
    }

    // ---- fallback label scan (only if not converged in 10 iters) ----
    if (!done) {
        s0m = 3.4e38f; s1m = 3.4e38f; s2m = 3.4e38f; s3m = 3.4e38f;
#pragma unroll 2
        for (int kl = 0; kl < Kn; kl++) {
            const float* mk = &s_m[kl * MSTR];
            s0m = fminf(s0m, dchain_row(f0, mk));
            s1m = fminf(s1m, dchain_row(f1, mk));
            s2m = fminf(s2m, dchain_row(f2, mk));
            s3m = fminf(s3m, dchain_row(f3, mk));
        }
    }

    // ---- emit labels (argmin recovered only for labeled points) + means ----
    float* ob = out + (size_t)b * Pn + pbase;
    ob[0] = (s0m < t0) ? (float)(find_argmin(f0, s0m, s_m) + 1) : 0.0f;
    ob[1] = (s1m < t1) ? (float)(find_argmin(f1, s1m, s_m) + 1) : 0.0f;
    ob[2] = (s2m < t2) ? (float)(find_argmin(f2, s2m, s_m) + 1) : 0.0f;
    ob[3] = (s3m < t3) ? (float)(find_argmin(f3, s3m, s_m) + 1) : 0.0f;
    if (blockIdx.x == 0) {
        for (int i = threadIdx.x; i < Kn * Cn; i += TPB) {
            int o = Bn * Pn + b * Kn * Cn + i;
            if (o < out_size)
                out[o] = -0.5f * s_m[(i / Cn) * MSTR + (i % Cn)];
        }
    }

    // ---- epilogue: restore num/den[0] zeros for the next graph replay ----
    batchbar(b);
    {
        int base = b * Kn * Cn;
        for (int i = blockIdx.x * TPB + threadIdx.x; i < Kn * Cn; i += XB * TPB)
            g_num[0][base + i] = 0.0f;
        for (int i = blockIdx.x * TPB + threadIdx.x; i < Kn; i += XB * TPB)
            g_den[0][b * Kn + i] = 0.0f;
    }
}

extern "C" void kernel_launch(void* const* d_in, const int* in_sizes, int n_in,
                              void* d_out, int out_size) {
    const float* feat = (const float*)d_in[0];
    const void*  sidx = d_in[1];
    float* out = (float*)d_out;

    dim3 grid(XB, Bn);
    fused_kernel<<<grid, TPB>>>(feat, sidx, out, out_size);
}